// round 4
// baseline (speedup 1.0000x reference)
#include <cuda_runtime.h>
#include <cstdint>

#define BB 64
#define SS 196
#define HALFS 98
#define OO 10
#define SLAB 4096           // float2 per 64x64 slab
#define SLAB_BYTES 32768

__device__ __align__(128) float2 g_coresT[SS * SLAB];
__device__ float g_vecL[BB][64];
__device__ float g_vecR[BB][64];

// ---------------------------------------------------------------------------
__device__ __forceinline__ uint32_t smem_u32(const void* p) {
    uint32_t a;
    asm("{ .reg .u64 t; cvta.to.shared.u64 t, %1; cvt.u32.u64 %0, t; }"
        : "=r"(a) : "l"(p));
    return a;
}
__device__ __forceinline__ void mbar_init(uint32_t a, uint32_t cnt) {
    asm volatile("mbarrier.init.shared.b64 [%0], %1;" :: "r"(a), "r"(cnt) : "memory");
}
__device__ __forceinline__ void mbar_arrive(uint32_t a) {
    asm volatile("mbarrier.arrive.shared.b64 _, [%0];" :: "r"(a) : "memory");
}
__device__ __forceinline__ void mbar_expect_tx(uint32_t a, uint32_t bytes) {
    asm volatile("mbarrier.arrive.expect_tx.shared.b64 _, [%0], %1;"
                 :: "r"(a), "r"(bytes) : "memory");
}
__device__ __forceinline__ void mbar_wait(uint32_t a, uint32_t phase) {
    asm volatile(
        "{\n\t.reg .pred P;\n\t"
        "W_%=:\n\t"
        "mbarrier.try_wait.parity.shared.b64 P, [%0], %1;\n\t"
        "@!P bra W_%=;\n\t}"
        :: "r"(a), "r"(phase) : "memory");
}
__device__ __forceinline__ void bulk_g2s(uint32_t dst, const void* src,
                                         uint32_t bytes, uint32_t mbar) {
    asm volatile(
        "cp.async.bulk.shared::cluster.global.mbarrier::complete_tx::bytes "
        "[%0], [%1], %2, [%3];"
        :: "r"(dst), "l"(src), "r"(bytes), "r"(mbar) : "memory");
}

// ---------------------------------------------------------------------------
// Kernel 1: transpose ONLY the right-half slabs s in [98,196).
// ---------------------------------------------------------------------------
__global__ __launch_bounds__(256) void transpose_kernel(const float2* __restrict__ cores)
{
    __shared__ float2 tile[64][65];
    const int s = blockIdx.x + HALFS;
    const float2* src = cores + (size_t)s * SLAB;
    float2* dst = g_coresT + (size_t)s * SLAB;
    const int t = threadIdx.x;

    float2 v[16];
#pragma unroll
    for (int i = 0; i < 16; i++) v[i] = src[t + i * 256];      // MLP=16
#pragma unroll
    for (int i = 0; i < 16; i++) {
        int idx = t + i * 256;
        tile[idx >> 6][idx & 63] = v[i];
    }
    __syncthreads();
#pragma unroll
    for (int i = 0; i < 16; i++) {
        int idx = t + i * 256;
        v[i] = tile[idx & 63][idx >> 6];
    }
#pragma unroll
    for (int i = 0; i < 16; i++) dst[t + i * 256] = v[i];
}

// ---------------------------------------------------------------------------
// Kernel 2: 64 CTAs x 256 threads. CTA = (half, batch-pair b0,b0+1).
// Thread (g = m-quarter, n = column): reads C once, FMAs for both batches.
// Prefetch of step k+1's C is SPLIT: half interleaved with step k's FMAs,
// half between the two barriers (hides the combiner tail).
// Combiners = lane<8 of every warp (spread across all SMSPs).
// ---------------------------------------------------------------------------
__global__ __launch_bounds__(256, 1) void chain_kernel(const float* __restrict__ x,
                                                       const float2* __restrict__ cores)
{
    extern __shared__ __align__(128) unsigned char dynsm[];
    float2*   Cbuf = (float2*)dynsm;                                  // 4 x 32KB slots
    float4*   part = (float4*)(dynsm + 4 * SLAB_BYTES);               // [4][64]
    float2*   lvb  = (float2*)(dynsm + 4 * SLAB_BYTES + 4096);        // [64] (b0,b1)
    float2*   xsh  = (float2*)(dynsm + 4 * SLAB_BYTES + 4096 + 512);  // [2][98]
    uint64_t* bars = (uint64_t*)(dynsm + 4 * SLAB_BYTES + 4096 + 512 + 2 * HALFS * 8);
    const uint32_t bbase = smem_u32(bars);  // +0/+8 full p0/p1, +16/+24 empty p0/p1
    const uint32_t cb0   = smem_u32(Cbuf);

    const int t = threadIdx.x;
    const int n = t & 63;
    const int g = t >> 6;
    const int half = blockIdx.x >> 5;
    const int b0 = (blockIdx.x & 31) * 2;
    const bool comb = (t & 31) < 8;                 // 64 combiners, 8 per warp
    const int nc = ((t >> 5) << 3) | (t & 7);       // combiner's column

    const float2* xf = (const float2*)x;   // [B][S]
    for (int k = t; k < HALFS; k += 256) {
        int s = half ? (SS - 1 - k) : k;
        xsh[k]         = xf[(b0 + 0) * SS + s];
        xsh[HALFS + k] = xf[(b0 + 1) * SS + s];
    }
    if (t < 64) lvb[t] = make_float2(t == 0 ? 1.f : 0.f, t == 0 ? 1.f : 0.f);

    const float2* s0 = half ? (g_coresT + (size_t)(SS - 1) * SLAB) : cores;
    const long sstride = half ? -(long)SLAB : (long)SLAB;

    if (t == 0) {
        mbar_init(bbase + 0, 1);   mbar_init(bbase + 8, 1);    // full (tx-based)
        mbar_init(bbase + 16, 8);  mbar_init(bbase + 24, 8);   // empty (8 warps)
    }
    __syncthreads();

    if (t == 0) {   // prologue: pairs 0 (slots 0,1) and 1 (slots 2,3)
        mbar_expect_tx(bbase + 0, 2 * SLAB_BYTES);
        bulk_g2s(cb0 + 0 * SLAB_BYTES, s0 + 0 * sstride, SLAB_BYTES, bbase + 0);
        bulk_g2s(cb0 + 1 * SLAB_BYTES, s0 + 1 * sstride, SLAB_BYTES, bbase + 0);
        mbar_expect_tx(bbase + 8, 2 * SLAB_BYTES);
        bulk_g2s(cb0 + 2 * SLAB_BYTES, s0 + 2 * sstride, SLAB_BYTES, bbase + 8);
        bulk_g2s(cb0 + 3 * SLAB_BYTES, s0 + 3 * sstride, SLAB_BYTES, bbase + 8);
    }

    float2 A[16], Bf[16];
    mbar_wait(bbase + 0, 0);
    {
        const float2* P = Cbuf + g * 1024 + n;
#pragma unroll
        for (int mm = 0; mm < 16; mm++) A[mm] = P[mm * 64];
    }

    // PAR = K&1 (compile-time). Even K: prefetch always valid, handles ring
    // arrivals/refill. Odd K: waits next pair's full barrier (when k+1<98).
#define CHAIN_STEP(CUR, NXT, K, PAR)                                            \
    {                                                                           \
        const int kp1 = (K) + 1;                                                \
        const bool pf = (PAR == 0) ? true : (kp1 < HALFS);                      \
        if (PAR == 1 && pf) {            /* kp1 even: new pair begins */        \
            int P = kp1 >> 1;                                                   \
            mbar_wait(bbase + (P & 1) * 8, (P >> 1) & 1);                       \
        }                                                                       \
        const float2* Ns = Cbuf + (kp1 & 3) * SLAB + g * 1024 + n;              \
        if (pf) {                        /* first half of prefetch */           \
            _Pragma("unroll")                                                   \
            for (int mm = 0; mm < 8; mm++) NXT[mm] = Ns[mm * 64];               \
        }                                                                       \
        const float4* lv4 = (const float4*)(lvb + g * 16);                      \
        float sx0 = 0.f, sy0 = 0.f, sx1 = 0.f, sy1 = 0.f;                       \
        _Pragma("unroll")                                                       \
        for (int q = 0; q < 8; q++) {                                           \
            float4 l4 = lv4[q];                                                 \
            float2 c0 = CUR[2 * q], c1 = CUR[2 * q + 1];                        \
            sx0 = fmaf(l4.x, c0.x, sx0);  sy0 = fmaf(l4.x, c0.y, sy0);          \
            sx1 = fmaf(l4.y, c0.x, sx1);  sy1 = fmaf(l4.y, c0.y, sy1);          \
            sx0 = fmaf(l4.z, c1.x, sx0);  sy0 = fmaf(l4.z, c1.y, sy0);          \
            sx1 = fmaf(l4.w, c1.x, sx1);  sy1 = fmaf(l4.w, c1.y, sy1);          \
        }                                                                       \
        part[g * 64 + n] = make_float4(sx0, sy0, sx1, sy1);                     \
        __syncthreads();                                                        \
        if (pf) {                        /* second half hides combine */        \
            _Pragma("unroll")                                                   \
            for (int mm = 8; mm < 16; mm++) NXT[mm] = Ns[mm * 64];              \
        }                                                                       \
        if (comb) {                                                             \
            float4 p0 = part[nc], p1 = part[64 + nc];                           \
            float4 p2 = part[128 + nc], p3 = part[192 + nc];                    \
            float Sx0 = (p0.x + p1.x) + (p2.x + p3.x);                          \
            float Sy0 = (p0.y + p1.y) + (p2.y + p3.y);                          \
            float Sx1 = (p0.z + p1.z) + (p2.z + p3.z);                          \
            float Sy1 = (p0.w + p1.w) + (p2.w + p3.w);                          \
            float2 x0 = xsh[(K)], x1 = xsh[HALFS + (K)];                        \
            lvb[nc] = make_float2(fmaf(x0.x, Sx0, x0.y * Sy0),                  \
                                  fmaf(x1.x, Sx1, x1.y * Sy1));                 \
        }                                                                       \
        if (PAR == 0) {                  /* pair q=K/2 fully consumed */        \
            int q = (K) >> 1;                                                   \
            if ((t & 31) == 0) mbar_arrive(bbase + 16 + (q & 1) * 8);           \
            if (t == 0 && q + 2 < HALFS / 2) {                                  \
                mbar_wait(bbase + 16 + (q & 1) * 8, (q >> 1) & 1);              \
                mbar_expect_tx(bbase + (q & 1) * 8, 2 * SLAB_BYTES);            \
                int k0 = 2 * q + 4;                                             \
                bulk_g2s(cb0 + (k0 & 3) * SLAB_BYTES,                           \
                         s0 + (long)k0 * sstride, SLAB_BYTES,                   \
                         bbase + (q & 1) * 8);                                  \
                bulk_g2s(cb0 + ((k0 + 1) & 3) * SLAB_BYTES,                     \
                         s0 + (long)(k0 + 1) * sstride, SLAB_BYTES,             \
                         bbase + (q & 1) * 8);                                  \
            }                                                                   \
        }                                                                       \
        __syncthreads();                                                        \
    }

#pragma unroll 1
    for (int k = 0; k < HALFS; k += 2) {
        CHAIN_STEP(A, Bf, k, 0);
        CHAIN_STEP(Bf, A, k + 1, 1);
    }
#undef CHAIN_STEP

    if (t < 64) {
        float2 v = lvb[n];
        if (half == 0) { g_vecL[b0][n] = v.x; g_vecL[b0 + 1][n] = v.y; }
        else           { g_vecR[b0][n] = v.x; g_vecR[b0 + 1][n] = v.y; }
    }
}

// ---------------------------------------------------------------------------
// Kernel 3: out[b,o] = sum_{l,r} L[b,l] * oc[o,l,r] * R[b,r]
// ---------------------------------------------------------------------------
__global__ __launch_bounds__(64) void out_kernel(const float* __restrict__ oc,
                                                 float* __restrict__ out)
{
    const int b = blockIdx.x;
    const int r = threadIdx.x;
    __shared__ float Ls[64];
    __shared__ float red[2][OO];

    Ls[r] = g_vecL[b][r];
    const float R = g_vecR[b][r];
    __syncthreads();

    for (int o = 0; o < OO; o++) {
        float acc = 0.f;
        const float* m = oc + o * 4096 + r;
#pragma unroll 8
        for (int l = 0; l < 64; l++) acc = fmaf(Ls[l], m[l * 64], acc);
        acc *= R;
#pragma unroll
        for (int off = 16; off; off >>= 1)
            acc += __shfl_down_sync(0xffffffffu, acc, off);
        if ((r & 31) == 0) red[r >> 5][o] = acc;
    }
    __syncthreads();
    if (r < OO) out[b * OO + r] = red[0][r] + red[1][r];
}

// ---------------------------------------------------------------------------
extern "C" void kernel_launch(void* const* d_in, const int* in_sizes, int n_in,
                              void* d_out, int out_size)
{
    const float* x = nullptr;
    const float* cores = nullptr;
    const float* oc = nullptr;
    for (int i = 0; i < n_in; i++) {
        if (in_sizes[i] == BB * SS * 2)         x = (const float*)d_in[i];
        else if (in_sizes[i] == SS * SLAB * 2)  cores = (const float*)d_in[i];
        else if (in_sizes[i] == OO * 4096)      oc = (const float*)d_in[i];
    }

    const int DYN_SMEM = 4 * SLAB_BYTES + 4096 + 512 + 2 * HALFS * 8 + 64;
    cudaFuncSetAttribute(chain_kernel, cudaFuncAttributeMaxDynamicSharedMemorySize, DYN_SMEM);

    transpose_kernel<<<SS - HALFS, 256>>>((const float2*)cores);
    chain_kernel<<<64, 256, DYN_SMEM>>>(x, (const float2*)cores);
    out_kernel<<<BB, 64>>>(oc, (float*)d_out);
}

// round 5
// speedup vs baseline: 1.1323x; 1.1323x over previous
#include <cuda_runtime.h>
#include <cstdint>

#define SS 196
#define HALFS 98
#define BB 64
#define OO 10
#define SLAB 4096           // float2 per 64x64 slab
#define SLAB_BYTES 32768
#define RING 6
#define NT 288              // 8 worker warps + 1 control warp

__device__ __align__(128) float2 g_coresT[SS * SLAB];
__device__ float g_vecL[BB][64];
__device__ float g_vecR[BB][64];

// ---------------------------------------------------------------------------
__device__ __forceinline__ uint32_t smem_u32(const void* p) {
    uint32_t a;
    asm("{ .reg .u64 t; cvta.to.shared.u64 t, %1; cvt.u32.u64 %0, t; }"
        : "=r"(a) : "l"(p));
    return a;
}
__device__ __forceinline__ void mbar_init(uint32_t a, uint32_t cnt) {
    asm volatile("mbarrier.init.shared.b64 [%0], %1;" :: "r"(a), "r"(cnt) : "memory");
}
__device__ __forceinline__ void mbar_arrive(uint32_t a) {
    asm volatile("mbarrier.arrive.shared.b64 _, [%0];" :: "r"(a) : "memory");
}
__device__ __forceinline__ void mbar_expect_tx(uint32_t a, uint32_t bytes) {
    asm volatile("mbarrier.arrive.expect_tx.shared.b64 _, [%0], %1;"
                 :: "r"(a), "r"(bytes) : "memory");
}
__device__ __forceinline__ void mbar_wait(uint32_t a, uint32_t phase) {
    asm volatile(
        "{\n\t.reg .pred P;\n\t"
        "W_%=:\n\t"
        "mbarrier.try_wait.parity.shared.b64 P, [%0], %1;\n\t"
        "@!P bra W_%=;\n\t}"
        :: "r"(a), "r"(phase) : "memory");
}
__device__ __forceinline__ void bulk_g2s(uint32_t dst, const void* src,
                                         uint32_t bytes, uint32_t mbar) {
    asm volatile(
        "cp.async.bulk.shared::cluster.global.mbarrier::complete_tx::bytes "
        "[%0], [%1], %2, [%3];"
        :: "r"(dst), "l"(src), "r"(bytes), "r"(mbar) : "memory");
}

#define BAR_SYNC(ID)   asm volatile("bar.sync "  #ID ", 288;" ::: "memory")
#define BAR_ARRIVE(ID) asm volatile("bar.arrive " #ID ", 288;" ::: "memory")

// ---------------------------------------------------------------------------
// Kernel 1: transpose right-half slabs, 4 CTAs per slab (16-row strips).
// ---------------------------------------------------------------------------
__global__ __launch_bounds__(128) void transpose_kernel(const float2* __restrict__ cores)
{
    __shared__ float2 tile[16][65];
    const int s  = (blockIdx.x >> 2) + HALFS;
    const int lb = (blockIdx.x & 3) * 16;
    const float2* src = cores + (size_t)s * SLAB + (size_t)lb * 64;
    float2* dst = g_coresT + (size_t)s * SLAB + lb;
    const int t = threadIdx.x;

    float2 v[8];
#pragma unroll
    for (int i = 0; i < 8; i++) v[i] = src[t + i * 128];       // MLP=8
#pragma unroll
    for (int i = 0; i < 8; i++) {
        int idx = t + i * 128;
        tile[idx >> 6][idx & 63] = v[i];
    }
    __syncthreads();
#pragma unroll
    for (int i = 0; i < 8; i++) {
        int idx = t + i * 128;
        v[i] = tile[idx & 15][idx >> 4];
    }
#pragma unroll
    for (int i = 0; i < 8; i++) {
        int idx = t + i * 128;
        dst[(idx >> 4) * 64 + (idx & 15)] = v[i];
    }
}

// ---------------------------------------------------------------------------
// Kernel 2: warp-specialized chain. 64 CTAs, 288 threads.
// Workers (w<8): thread (g = m-quarter, n) -> 64 FFMA/step, partials to smem.
// Control (w=8): combine + x-fold + lv write, all mbar waits, TMA ring.
// Barriers: 1 = parts ready (A), 2 = lv ready (B), 3 = slab certified (C).
// ---------------------------------------------------------------------------
__global__ __launch_bounds__(NT, 1) void chain_kernel(const float* __restrict__ x,
                                                      const float2* __restrict__ cores)
{
    extern __shared__ __align__(128) unsigned char dynsm[];
    float2* ring = (float2*)dynsm;                                     // 6 x 32KB
    float4* part = (float4*)(dynsm + RING * SLAB_BYTES);               // [4][64]
    float2* lvb  = (float2*)(dynsm + RING * SLAB_BYTES + 4096);        // [2][64]
    float2* xsh  = (float2*)(dynsm + RING * SLAB_BYTES + 4096 + 1024); // [2][98]
    __shared__ __align__(8) uint64_t full_mb[RING];
    __shared__ __align__(8) uint64_t empty_mb[RING];

    const int t = threadIdx.x;
    const int w = t >> 5;
    const int lane = t & 31;
    const int half = blockIdx.x >> 5;
    const int b0 = (blockIdx.x & 31) * 2;

    const uint32_t fb = smem_u32(full_mb);
    const uint32_t eb = smem_u32(empty_mb);
    const uint32_t ru = smem_u32(ring);

    const float2* s0 = half ? (g_coresT + (size_t)(SS - 1) * SLAB) : cores;
    const long sstride = half ? -(long)SLAB : (long)SLAB;

    const float2* xf = (const float2*)x;     // [B][S]
    for (int k = t; k < HALFS; k += NT) {
        int s = half ? (SS - 1 - k) : k;
        xsh[k]         = xf[(b0 + 0) * SS + s];
        xsh[HALFS + k] = xf[(b0 + 1) * SS + s];
    }
    if (t < 64) lvb[t] = make_float2(t == 0 ? 1.f : 0.f, t == 0 ? 1.f : 0.f);
    if (t == 0) {
        for (int j = 0; j < RING; j++) {
            mbar_init(fb + 8 * j, 1);
            mbar_init(eb + 8 * j, 1);
        }
    }
    __syncthreads();

    if (t == 0) {       // prologue: slabs 0..4 into slots 0..4
        for (int s = 0; s < 5; s++) {
            mbar_expect_tx(fb + 8 * s, SLAB_BYTES);
            bulk_g2s(ru + s * SLAB_BYTES, s0 + (long)s * sstride,
                     SLAB_BYTES, fb + 8 * s);
        }
    }
    mbar_wait(fb + 0, 0);                    // slab 0 for everyone
    if (w == 8) {
        if (lane == 0) { mbar_wait(fb + 8, 0); mbar_wait(fb + 16, 0); } // slabs 1,2
        __syncwarp();
    }
    __syncthreads();

    if (w < 8) {
        // ---------------- workers ----------------
        const int g = w >> 1;
        const int n = (w & 1) * 32 + lane;
        const int coff = g * 1024 + n;        // float2 offset into a slab
        float2 A[16], Bf[16];
        {
            const float2* P = ring + coff;
#pragma unroll
            for (int i = 0; i < 16; i++) A[i] = P[i * 64];
        }
        int slot1 = 1;                        // ring slot holding slab k+1

#define WSTEP(CUR, NXT, K)                                                  \
        {                                                                   \
            const float4* lv4 = (const float4*)(lvb + ((K) & 1) * 64);      \
            float sx0 = 0.f, sy0 = 0.f, sx1 = 0.f, sy1 = 0.f;               \
            _Pragma("unroll")                                               \
            for (int i = 0; i < 8; i++) {                                   \
                float4 L = lv4[g * 8 + i];                                  \
                float2 c0 = CUR[2 * i], c1 = CUR[2 * i + 1];                \
                sx0 = fmaf(L.x, c0.x, sx0);  sy0 = fmaf(L.x, c0.y, sy0);    \
                sx1 = fmaf(L.y, c0.x, sx1);  sy1 = fmaf(L.y, c0.y, sy1);    \
                sx0 = fmaf(L.z, c1.x, sx0);  sy0 = fmaf(L.z, c1.y, sy0);    \
                sx1 = fmaf(L.w, c1.x, sx1);  sy1 = fmaf(L.w, c1.y, sy1);    \
            }                                                               \
            part[g * 64 + n] = make_float4(sx0, sy0, sx1, sy1);             \
            BAR_ARRIVE(1);                                                  \
            if ((K) < HALFS - 1) {       /* prefetch slab K+1 (certified) */\
                const float2* Ns = ring + slot1 * SLAB + coff;              \
                _Pragma("unroll")                                           \
                for (int i = 0; i < 16; i++) NXT[i] = Ns[i * 64];           \
            }                                                               \
            slot1 = (slot1 == RING - 1) ? 0 : slot1 + 1;                    \
            BAR_SYNC(2);                 /* lv[K+1] ready */                \
            BAR_SYNC(3);                 /* slab K+2 certified */           \
        }

#pragma unroll 1
        for (int k = 0; k < HALFS; k += 2) {
            WSTEP(A, Bf, k);
            WSTEP(Bf, A, k + 1);
        }
#undef WSTEP

        if (t < 64) {                       // final lv in buffer 0
            float2 v = lvb[t];
            if (half == 0) { g_vecL[b0][t] = v.x; g_vecL[b0 + 1][t] = v.y; }
            else           { g_vecR[b0][t] = v.x; g_vecR[b0 + 1][t] = v.y; }
        }
    } else {
        // ---------------- control warp ----------------
#pragma unroll 1
        for (int k = 0; k < HALFS; k++) {
            BAR_ARRIVE(3);                  // certify slab k+2 (verified at k-1)
            BAR_SYNC(1);                    // parts of step k ready
            {
                const int nb = (k + 1) & 1;
                float2 xa = xsh[k], xb = xsh[HALFS + k];
                float4 p0 = part[lane],       p1 = part[64 + lane];
                float4 p2 = part[128 + lane], p3 = part[192 + lane];
                float Sx0 = (p0.x + p1.x) + (p2.x + p3.x);
                float Sy0 = (p0.y + p1.y) + (p2.y + p3.y);
                float Sx1 = (p0.z + p1.z) + (p2.z + p3.z);
                float Sy1 = (p0.w + p1.w) + (p2.w + p3.w);
                lvb[nb * 64 + lane] = make_float2(fmaf(xa.x, Sx0, xa.y * Sy0),
                                                  fmaf(xb.x, Sx1, xb.y * Sy1));
                const int c2 = lane + 32;
                float4 q0 = part[c2],       q1 = part[64 + c2];
                float4 q2 = part[128 + c2], q3 = part[192 + c2];
                float Tx0 = (q0.x + q1.x) + (q2.x + q3.x);
                float Ty0 = (q0.y + q1.y) + (q2.y + q3.y);
                float Tx1 = (q0.z + q1.z) + (q2.z + q3.z);
                float Ty1 = (q0.w + q1.w) + (q2.w + q3.w);
                lvb[nb * 64 + c2] = make_float2(fmaf(xa.x, Tx0, xa.y * Ty0),
                                                fmaf(xb.x, Tx1, xb.y * Ty1));
            }
            BAR_ARRIVE(2);                  // release workers
            if (lane == 0) {                // hidden under workers' FMA phase
                int v = k + 3;              // verify slab k+3 -> feeds C_{k+1}
                if (v <= HALFS - 1)
                    mbar_wait(fb + 8 * (v % RING), (v / RING) & 1);
                mbar_arrive(eb + 8 * (k % RING));   // slot of slab k is free
                int s = k + 5;
                if (s <= HALFS - 1) {
                    if (s >= RING)
                        mbar_wait(eb + 8 * (s % RING), ((s / RING) - 1) & 1);
                    mbar_expect_tx(fb + 8 * (s % RING), SLAB_BYTES);
                    bulk_g2s(ru + (s % RING) * SLAB_BYTES,
                             s0 + (long)s * sstride, SLAB_BYTES,
                             fb + 8 * (s % RING));
                }
            }
        }
    }
}

// ---------------------------------------------------------------------------
// Kernel 3: out[b,o] = sum_{l,r} L[b,l] * oc[o,l,r] * R[b,r]
// ---------------------------------------------------------------------------
__global__ __launch_bounds__(64) void out_kernel(const float* __restrict__ oc,
                                                 float* __restrict__ out)
{
    const int b = blockIdx.x;
    const int r = threadIdx.x;
    __shared__ float Ls[64];
    __shared__ float red[2][OO];

    Ls[r] = g_vecL[b][r];
    const float R = g_vecR[b][r];
    __syncthreads();

    for (int o = 0; o < OO; o++) {
        float acc = 0.f;
        const float* m = oc + o * 4096 + r;
#pragma unroll 8
        for (int l = 0; l < 64; l++) acc = fmaf(Ls[l], m[l * 64], acc);
        acc *= R;
#pragma unroll
        for (int off = 16; off; off >>= 1)
            acc += __shfl_down_sync(0xffffffffu, acc, off);
        if ((r & 31) == 0) red[r >> 5][o] = acc;
    }
    __syncthreads();
    if (r < OO) out[b * OO + r] = red[0][r] + red[1][r];
}

// ---------------------------------------------------------------------------
extern "C" void kernel_launch(void* const* d_in, const int* in_sizes, int n_in,
                              void* d_out, int out_size)
{
    const float* x = nullptr;
    const float* cores = nullptr;
    const float* oc = nullptr;
    for (int i = 0; i < n_in; i++) {
        if (in_sizes[i] == BB * SS * 2)         x = (const float*)d_in[i];
        else if (in_sizes[i] == SS * SLAB * 2)  cores = (const float*)d_in[i];
        else if (in_sizes[i] == OO * 4096)      oc = (const float*)d_in[i];
    }

    const int DYN_SMEM = RING * SLAB_BYTES + 4096 + 1024 + 2 * HALFS * 8 + 64;
    cudaFuncSetAttribute(chain_kernel, cudaFuncAttributeMaxDynamicSharedMemorySize, DYN_SMEM);

    transpose_kernel<<<4 * (SS - HALFS), 128>>>((const float2*)cores);
    chain_kernel<<<64, NT, DYN_SMEM>>>(x, (const float2*)cores);
    out_kernel<<<BB, 64>>>(oc, (float*)d_out);
}

// round 6
// speedup vs baseline: 1.2487x; 1.1028x over previous
#include <cuda_runtime.h>
#include <cstdint>

#define BB 64
#define SS 196
#define HALFS 98
#define OO 10
#define SLAB 4096            // float2 per 64x64 slab
#define SLAB_BYTES 32768
#define RING 6
#define NT 160               // 4 worker warps + 1 TMA warp

__device__ __align__(128) float2 g_coresT[SS * SLAB];
__device__ float g_vecL[BB][64];
__device__ float g_vecR[BB][64];

// ---------------------------------------------------------------------------
__device__ __forceinline__ uint32_t smem_u32(const void* p) {
    uint32_t a;
    asm("{ .reg .u64 t; cvta.to.shared.u64 t, %1; cvt.u32.u64 %0, t; }"
        : "=r"(a) : "l"(p));
    return a;
}
__device__ __forceinline__ void mbar_init(uint32_t a, uint32_t cnt) {
    asm volatile("mbarrier.init.shared.b64 [%0], %1;" :: "r"(a), "r"(cnt) : "memory");
}
__device__ __forceinline__ void mbar_expect_tx(uint32_t a, uint32_t bytes) {
    asm volatile("mbarrier.arrive.expect_tx.shared.b64 _, [%0], %1;"
                 :: "r"(a), "r"(bytes) : "memory");
}
__device__ __forceinline__ void mbar_wait(uint32_t a, uint32_t phase) {
    asm volatile(
        "{\n\t.reg .pred P;\n\t"
        "W_%=:\n\t"
        "mbarrier.try_wait.parity.shared.b64 P, [%0], %1;\n\t"
        "@!P bra W_%=;\n\t}"
        :: "r"(a), "r"(phase) : "memory");
}
__device__ __forceinline__ void bulk_g2s(uint32_t dst, const void* src,
                                         uint32_t bytes, uint32_t mbar) {
    asm volatile(
        "cp.async.bulk.shared::cluster.global.mbarrier::complete_tx::bytes "
        "[%0], [%1], %2, [%3];"
        :: "r"(dst), "l"(src), "r"(bytes), "r"(mbar) : "memory");
}

#define BAR_SYNC1()   asm volatile("bar.sync 1, 288;"   ::: "memory")
#define BAR_ARRIVE1() asm volatile("bar.arrive 1, 288;" ::: "memory")
#define BAR_SYNC2()   asm volatile("bar.sync 2, 288;"   ::: "memory")
#define BAR_ARRIVE2() asm volatile("bar.arrive 2, 288;" ::: "memory")

// ---------------------------------------------------------------------------
// Kernel 1: transpose right-half slabs, 4 CTAs per slab (16-row strips).
// ---------------------------------------------------------------------------
__global__ __launch_bounds__(128) void transpose_kernel(const float2* __restrict__ cores)
{
    __shared__ float2 tile[16][65];
    const int s  = (blockIdx.x >> 2) + HALFS;
    const int lb = (blockIdx.x & 3) * 16;
    const float2* src = cores + (size_t)s * SLAB + (size_t)lb * 64;
    float2* dst = g_coresT + (size_t)s * SLAB + lb;
    const int t = threadIdx.x;

    float2 v[8];
#pragma unroll
    for (int i = 0; i < 8; i++) v[i] = src[t + i * 128];
#pragma unroll
    for (int i = 0; i < 8; i++) {
        int idx = t + i * 128;
        tile[idx >> 6][idx & 63] = v[i];
    }
    __syncthreads();
#pragma unroll
    for (int i = 0; i < 8; i++) {
        int idx = t + i * 128;
        v[i] = tile[idx & 15][idx >> 4];
    }
#pragma unroll
    for (int i = 0; i < 8; i++) {
        int idx = t + i * 128;
        dst[(idx >> 4) * 64 + (idx & 15)] = v[i];
    }
}

// ---------------------------------------------------------------------------
// Kernel 2: 64 CTAs x 160 threads (4 worker warps + 1 TMA warp).
// Worker warp w: lane = (g = m-half, c), column n = w*16 + c.
// Per step, per batch: 32 C-float2 x lv FMAs, shfl.bfly(16) combine, STS lv.
// Barriers: id1 = lv_b0 published, id2 = lv_b1 published (count 288:
// workers arrive+sync, TMA warp syncs both after certifying slab k+2).
// ---------------------------------------------------------------------------
__global__ __launch_bounds__(NT, 1) void chain_kernel(const float* __restrict__ x,
                                                      const float2* __restrict__ cores)
{
    extern __shared__ __align__(128) unsigned char dynsm[];
    float2* ring  = (float2*)dynsm;                               // 6 x 32KB
    float*  lvsm  = (float*)(dynsm + RING * SLAB_BYTES);          // lv0[2][72], lv1[2][72]
    float2* xsh   = (float2*)(dynsm + RING * SLAB_BYTES + 1152);  // [2][98]
    uint64_t* mbp = (uint64_t*)(dynsm + RING * SLAB_BYTES + 1152 + 1568);

    const uint32_t fb = smem_u32(mbp);
    const uint32_t ru = smem_u32(ring);

    const int t    = threadIdx.x;
    const int w    = t >> 5;
    const int lane = t & 31;
    const int g    = lane >> 4;
    const int c    = lane & 15;
    const int half = blockIdx.x >> 5;
    const int b0   = (blockIdx.x & 31) * 2;

    const float2* s0 = half ? (g_coresT + (size_t)(SS - 1) * SLAB) : cores;
    const long sstride = half ? -(long)SLAB : (long)SLAB;

    // stage x in iteration order
    const float2* xf = (const float2*)x;        // [B][S]
    for (int k = t; k < HALFS; k += NT) {
        int s = half ? (SS - 1 - k) : k;
        xsh[k]         = xf[(b0 + 0) * SS + s];
        xsh[HALFS + k] = xf[(b0 + 1) * SS + s];
    }
    // init lv buffer 0 (padded layout: half h at offset h*36)
    if (t < 64) {
        int h = t >> 5, p = t & 31;
        float v = (t == 0) ? 1.f : 0.f;
        lvsm[h * 36 + p]       = v;   // batch0, buf0
        lvsm[144 + h * 36 + p] = v;   // batch1, buf0
    }
    if (t == 0)
        for (int j = 0; j < RING; j++) mbar_init(fb + 8 * j, 1);
    __syncthreads();

    if (w == 4 && lane == 0) {            // prologue: slabs 0..5
        for (int s = 0; s < RING; s++) {
            mbar_expect_tx(fb + 8 * s, SLAB_BYTES);
            bulk_g2s(ru + s * SLAB_BYTES, s0 + (long)s * sstride,
                     SLAB_BYTES, fb + 8 * s);
        }
        mbar_wait(fb + 0, 0);             // slab 0 (reg load)
        mbar_wait(fb + 8, 0);             // slab 1 (step-0 prefetch)
    }
    __syncthreads();

    if (w < 4) {
        // ============================ workers ============================
        const int n = w * 16 + c;
        const int coff = g * 2048 + n;    // float2 offset of (m = g*32, n)
        const int hh = w >> 1;            // n >> 5
        const int sto = hh * 36 + (w & 1) * 16 + c;   // lv store offset

        float2 A[32], B[32];
        {
            const float2* P = ring + coff;
#pragma unroll
            for (int i = 0; i < 32; i++) A[i] = P[i * 64];
        }
        int slotn = 1;                    // ring slot of slab k+1

#define WSTEP(CUR, NXT, K, PAR)                                              \
        {                                                                    \
            /* ---------- batch 0 ---------- */                              \
            const float4* lv0 = (const float4*)(lvsm + (PAR) * 72 + g * 36); \
            float4 L[8];                                                     \
            _Pragma("unroll")                                                \
            for (int q = 0; q < 8; q++) L[q] = lv0[q];                       \
            float sx0 = 0.f, sx1 = 0.f, sy0 = 0.f, sy1 = 0.f;                \
            _Pragma("unroll")                                                \
            for (int q = 0; q < 8; q++) {                                    \
                float2 c0 = CUR[4*q+0], c1 = CUR[4*q+1];                     \
                float2 c2 = CUR[4*q+2], c3 = CUR[4*q+3];                     \
                sx0 = fmaf(L[q].x, c0.x, sx0); sy0 = fmaf(L[q].x, c0.y, sy0);\
                sx1 = fmaf(L[q].y, c1.x, sx1); sy1 = fmaf(L[q].y, c1.y, sy1);\
                sx0 = fmaf(L[q].z, c2.x, sx0); sy0 = fmaf(L[q].z, c2.y, sy0);\
                sx1 = fmaf(L[q].w, c3.x, sx1); sy1 = fmaf(L[q].w, c3.y, sy1);\
            }                                                                \
            float Sx = sx0 + sx1, Sy = sy0 + sy1;                            \
            float oxx = __shfl_xor_sync(0xffffffffu, Sx, 16);                \
            float oyy = __shfl_xor_sync(0xffffffffu, Sy, 16);                \
            /* prefetch slab K+1 first half in the shfl shadow */            \
            const float2* Ns = ring + slotn * SLAB + coff;                   \
            const bool pf = (K) < HALFS - 1;                                 \
            if (pf) {                                                        \
                _Pragma("unroll")                                            \
                for (int i = 0; i < 16; i++) NXT[i] = Ns[i * 64];            \
            }                                                                \
            Sx += oxx; Sy += oyy;                                            \
            {                                                                \
                float2 xk = xsh[(K)];                                        \
                float nv = fmaf(xk.x, Sx, xk.y * Sy);                        \
                if (g == 0) lvsm[(1 - (PAR)) * 72 + sto] = nv;               \
            }                                                                \
            BAR_ARRIVE1();                                                   \
            if (pf) {                                                        \
                _Pragma("unroll")                                            \
                for (int i = 16; i < 32; i++) NXT[i] = Ns[i * 64];           \
            }                                                                \
            slotn = (slotn == RING - 1) ? 0 : slotn + 1;                     \
            /* ---------- batch 1 ---------- */                              \
            const float4* lv1 = (const float4*)(lvsm + 144 + (PAR) * 72 + g * 36); \
            _Pragma("unroll")                                                \
            for (int q = 0; q < 8; q++) L[q] = lv1[q];                       \
            sx0 = 0.f; sx1 = 0.f; sy0 = 0.f; sy1 = 0.f;                      \
            _Pragma("unroll")                                                \
            for (int q = 0; q < 8; q++) {                                    \
                float2 c0 = CUR[4*q+0], c1 = CUR[4*q+1];                     \
                float2 c2 = CUR[4*q+2], c3 = CUR[4*q+3];                     \
                sx0 = fmaf(L[q].x, c0.x, sx0); sy0 = fmaf(L[q].x, c0.y, sy0);\
                sx1 = fmaf(L[q].y, c1.x, sx1); sy1 = fmaf(L[q].y, c1.y, sy1);\
                sx0 = fmaf(L[q].z, c2.x, sx0); sy0 = fmaf(L[q].z, c2.y, sy0);\
                sx1 = fmaf(L[q].w, c3.x, sx1); sy1 = fmaf(L[q].w, c3.y, sy1);\
            }                                                                \
            Sx = sx0 + sx1; Sy = sy0 + sy1;                                  \
            oxx = __shfl_xor_sync(0xffffffffu, Sx, 16);                      \
            oyy = __shfl_xor_sync(0xffffffffu, Sy, 16);                      \
            Sx += oxx; Sy += oyy;                                            \
            {                                                                \
                float2 xk = xsh[HALFS + (K)];                                \
                float nv = fmaf(xk.x, Sx, xk.y * Sy);                        \
                if (g == 0) lvsm[144 + (1 - (PAR)) * 72 + sto] = nv;         \
            }                                                                \
            BAR_ARRIVE2();                                                   \
            BAR_SYNC1();     /* lv_b0[K+1] visible; slab K+2 certified */    \
            BAR_SYNC2();     /* lv_b1[K+1] visible */                        \
        }

#pragma unroll 1
        for (int k = 0; k < HALFS; k += 2) {
            WSTEP(A, B, k, 0);
            WSTEP(B, A, k + 1, 1);
        }
#undef WSTEP

        __syncthreads();
        if (t < 64) {        // final lv in buffer 0
            int h = t >> 5, p = t & 31;
            float v0 = lvsm[h * 36 + p];
            float v1 = lvsm[144 + h * 36 + p];
            if (half == 0) { g_vecL[b0][t] = v0; g_vecL[b0 + 1][t] = v1; }
            else           { g_vecR[b0][t] = v0; g_vecR[b0 + 1][t] = v1; }
        }
    } else {
        // ============================ TMA warp ============================
        int vs = 2, vph = 0;              // verify slot/phase for slab k+2
        int is = 0;                       // issue slot (= k % RING)
#pragma unroll 1
        for (int k = 0; k < HALFS; k++) {
            if (lane == 0 && k + 2 <= HALFS - 1)
                mbar_wait(fb + 8 * vs, vph);          // certify slab k+2
            BAR_SYNC1();
            BAR_SYNC2();
            if (lane == 0 && k + RING <= HALFS - 1) { // refill slot k%RING
                mbar_expect_tx(fb + 8 * is, SLAB_BYTES);
                bulk_g2s(ru + is * SLAB_BYTES,
                         s0 + (long)(k + RING) * sstride,
                         SLAB_BYTES, fb + 8 * is);
            }
            if (++vs == RING) { vs = 0; vph ^= 1; }
            if (++is == RING) is = 0;
        }
        __syncthreads();
    }
}

// ---------------------------------------------------------------------------
// Kernel 3: out[b,o] = sum_{l,r} L[b,l] * oc[o,l,r] * R[b,r]
// ---------------------------------------------------------------------------
__global__ __launch_bounds__(64) void out_kernel(const float* __restrict__ oc,
                                                 float* __restrict__ out)
{
    const int b = blockIdx.x;
    const int r = threadIdx.x;
    __shared__ float Ls[64];
    __shared__ float red[2][OO];

    Ls[r] = g_vecL[b][r];
    const float R = g_vecR[b][r];
    __syncthreads();

    for (int o = 0; o < OO; o++) {
        float acc = 0.f;
        const float* m = oc + o * 4096 + r;
#pragma unroll 8
        for (int l = 0; l < 64; l++) acc = fmaf(Ls[l], m[l * 64], acc);
        acc *= R;
#pragma unroll
        for (int off = 16; off; off >>= 1)
            acc += __shfl_down_sync(0xffffffffu, acc, off);
        if ((r & 31) == 0) red[r >> 5][o] = acc;
    }
    __syncthreads();
    if (r < OO) out[b * OO + r] = red[0][r] + red[1][r];
}

// ---------------------------------------------------------------------------
extern "C" void kernel_launch(void* const* d_in, const int* in_sizes, int n_in,
                              void* d_out, int out_size)
{
    const float* x = nullptr;
    const float* cores = nullptr;
    const float* oc = nullptr;
    for (int i = 0; i < n_in; i++) {
        if (in_sizes[i] == BB * SS * 2)         x = (const float*)d_in[i];
        else if (in_sizes[i] == SS * SLAB * 2)  cores = (const float*)d_in[i];
        else if (in_sizes[i] == OO * 4096)      oc = (const float*)d_in[i];
    }

    const int DYN_SMEM = RING * SLAB_BYTES + 1152 + 1568 + 64;
    cudaFuncSetAttribute(chain_kernel, cudaFuncAttributeMaxDynamicSharedMemorySize, DYN_SMEM);

    transpose_kernel<<<4 * (SS - HALFS), 128>>>((const float2*)cores);
    chain_kernel<<<64, NT, DYN_SMEM>>>(x, (const float2*)cores);
    out_kernel<<<BB, 64>>>(oc, (float*)d_out);
}